// round 15
// baseline (speedup 1.0000x reference)
#include <cuda_runtime.h>
#include <cuda_fp16.h>
#include <math.h>
#include <stdint.h>

#define B_ 4
#define S_ 2048
#define D_ 512
#define H_ 8
#define E_ 64

// ---------------- scratch (static, allocation-free) ----------------
__device__ __align__(16) uint32_t g_xh[B_*S_*D_/2];    // X, fp16 A-frag (k16)
__device__ __align__(16) uint32_t g_atth[B_*S_*D_/2];  // attn out, fp16 A-frag
__device__ __align__(16) uint32_t g_wqh[H_*D_*E_/2];   // weights, fp16 B-frag
__device__ __align__(16) uint32_t g_wkh[H_*D_*E_/2];
__device__ __align__(16) uint32_t g_wvh[H_*D_*E_/2];
__device__ __align__(16) uint32_t g_woh[D_*D_/2];
// fp16x2 fragment images for the attention kernel
__device__ __align__(16) uint32_t g_qb[B_*H_*S_*E_/2]; // Q A-frag, scaled
__device__ __align__(16) uint32_t g_kb[B_*H_*S_*E_/2]; // K B-frag per 64-key tile
__device__ __align__(16) uint32_t g_vb[B_*H_*S_*E_/2]; // V B-frag per 64-key tile

// ---------------- helpers ----------------
__device__ __forceinline__ uint32_t hpack(float hi, float lo) {
    uint32_t u;
    asm("cvt.rn.f16x2.f32 %0, %1, %2;" : "=r"(u) : "f"(hi), "f"(lo));
    return u;
}
__device__ __forceinline__ uint32_t hex2(uint32_t x) {   // 2^x on fp16x2 pair
    uint32_t y; asm("ex2.approx.f16x2 %0, %1;" : "=r"(y) : "r"(x)); return y;
}
__device__ __forceinline__ uint32_t hadd2(uint32_t a, uint32_t b) {
    uint32_t y; asm("add.rn.f16x2 %0, %1, %2;" : "=r"(y) : "r"(a), "r"(b)); return y;
}
__device__ __forceinline__ float2 h2f2(uint32_t u) {
    __half2 h = *(__half2*)&u;
    return __half22float2(h);
}
__device__ __forceinline__ void mma_f16(float c[4], uint32_t a0, uint32_t a1,
                                        uint32_t a2, uint32_t a3,
                                        uint32_t b0, uint32_t b1) {
    asm volatile(
        "mma.sync.aligned.m16n8k16.row.col.f32.f16.f16.f32 "
        "{%0,%1,%2,%3}, {%4,%5,%6,%7}, {%8,%9}, {%0,%1,%2,%3};"
        : "+f"(c[0]), "+f"(c[1]), "+f"(c[2]), "+f"(c[3])
        : "r"(a0), "r"(a1), "r"(a2), "r"(a3), "r"(b0), "r"(b1));
}
// fp16-accumulate variant: C/D are two packed f16x2 regs (rows g / g+8)
__device__ __forceinline__ void mma_f16h(uint32_t c[2], uint32_t a0, uint32_t a1,
                                         uint32_t a2, uint32_t a3,
                                         uint32_t b0, uint32_t b1) {
    asm volatile(
        "mma.sync.aligned.m16n8k16.row.col.f16.f16.f16.f16 "
        "{%0,%1}, {%2,%3,%4,%5}, {%6,%7}, {%0,%1};"
        : "+r"(c[0]), "+r"(c[1])
        : "r"(a0), "r"(a1), "r"(a2), "r"(a3), "r"(b0), "r"(b1));
}
__device__ __forceinline__ void cp16(uint32_t dst, const void* src) {
    asm volatile("cp.async.cg.shared.global [%0], [%1], 16;\n" :: "r"(dst), "l"(src));
}
__device__ __forceinline__ uint32_t s2u(const void* p) {
    uint32_t a;
    asm("{ .reg .u64 t; cvta.to.shared.u64 t, %1; cvt.u32.u64 %0, t; }" : "=r"(a) : "l"(p));
    return a;
}

// ---------------- kernel 0: fused prep (weights + X) -----------------------
__global__ __launch_bounds__(256) void prep_kernel(
    const float* __restrict__ x,
    const float* __restrict__ Wq, const float* __restrict__ Wk,
    const float* __restrict__ Wv, const float* __restrict__ Wo)
{
    int blk = blockIdx.x;
    if (blk < 512) {
        int i = blk*256 + threadIdx.x;       // 0..131071 (pairs along k)
        {   // Wq/Wk/Wv: [h][d][e], k=d(512), n=e(64)
            int h = i >> 14, p = i & 16383;
            int e = p & 63, d = (p >> 6) * 2;
            int kc = d >> 5, ks16 = (d >> 4) & 1, kk = d & 15;
            int half = kk >> 3, tg = (kk >> 1) & 3;
            int lane = (e & 7)*4 + tg, nt = e >> 3;
            int idx = h*16384 + kc*1024 + nt*128 + lane*4 + ks16*2 + half;
            size_t s0 = (size_t)h*32768 + (size_t)d*64 + e;
            g_wqh[idx] = hpack(Wq[s0 + 64], Wq[s0]);
            g_wkh[idx] = hpack(Wk[s0 + 64], Wk[s0]);
            g_wvh[idx] = hpack(Wv[s0 + 64], Wv[s0]);
        }
        {   // Wo: [d][n], k=d(512), n(512)
            int n = i & 511, d = (i >> 9) * 2;
            int kc = d >> 5, ks16 = (d >> 4) & 1, kk = d & 15;
            int half = kk >> 3, tg = (kk >> 1) & 3;
            int lane = (n & 7)*4 + tg, ntg = n >> 3;
            int idx = (ntg*16 + kc)*128 + lane*4 + ks16*2 + half;
            size_t s0 = (size_t)d*512 + n;
            g_woh[idx] = hpack(Wo[s0 + 512], Wo[s0]);
        }
    } else {
        int i = (blk - 512)*256 + threadIdx.x;   // uint4 index, 512K total
        int lane = i & 31, ksg = (i >> 5) & 31, rbg = i >> 10;
        int g = lane >> 2, tg = lane & 3;
        const float* src = x + ((size_t)rbg*16 + g)*D_ + ksg*16 + 2*tg;
        uint4 o;
        o.x = hpack(src[1],          src[0]);
        o.y = hpack(src[8*D_ + 1],   src[8*D_]);
        o.z = hpack(src[9],          src[8]);
        o.w = hpack(src[8*D_ + 9],   src[8*D_ + 8]);
        *(uint4*)&g_xh[(size_t)i*4] = o;
    }
}

// ---------------- kernel 1: QKV, fp16 m16n8k16, 3-stage cp.async -----------
#define QKV_STAGE_W 5120
#define QKV_SMEM_B  (3*QKV_STAGE_W*4)

__global__ __launch_bounds__(256, 2) void qkv_kernel(
    const float* __restrict__ bq, const float* __restrict__ bk,
    const float* __restrict__ bv)
{
    extern __shared__ uint32_t smu[];
    const int qb2 = blockIdx.x, h = blockIdx.y, b = blockIdx.z;
    const int bh = b*H_ + h;
    const int tid = threadIdx.x;
    const int wp = tid >> 5, lane = tid & 31;
    const int g = lane >> 2, tg = lane & 3;
    const uint32_t smem_base = s2u(smu);
    const size_t rbg0 = (size_t)b*(S_/16) + qb2*8;
    const size_t wbase = (size_t)h * 16384;

    float accq[8][4] = {}, acck[8][4] = {}, accv[8][4] = {};

    #define QKV_LOAD(stg, kc) do {                                            \
        uint32_t dst = smem_base + (stg)*(QKV_STAGE_W*4);                     \
        _Pragma("unroll")                                                     \
        for (int j = 0; j < 2; j++) {                                         \
            int i = tid + j*256;                                              \
            int rb = i >> 6, ks = (i >> 5) & 1, off = i & 31;                 \
            cp16(dst + i*16,                                                  \
                 g_xh + ((rbg0 + rb)*32 + (kc)*2 + ks)*128 + off*4);          \
        }                                                                     \
        cp16(dst + 8192  + tid*16, g_wqh + wbase + (kc)*1024 + tid*4);        \
        cp16(dst + 12288 + tid*16, g_wkh + wbase + (kc)*1024 + tid*4);        \
        cp16(dst + 16384 + tid*16, g_wvh + wbase + (kc)*1024 + tid*4);        \
        asm volatile("cp.async.commit_group;");                               \
    } while (0)

    QKV_LOAD(0, 0);
    QKV_LOAD(1, 1);
    for (int kc = 0; kc < 16; kc++) {
        if (kc + 1 < 16) asm volatile("cp.async.wait_group 1;");
        else             asm volatile("cp.async.wait_group 0;");
        __syncthreads();
        if (kc + 2 < 16) QKV_LOAD((kc + 2) % 3, kc + 2);

        const uint32_t* XA  = smu + (kc % 3)*QKV_STAGE_W;
        const uint32_t* WQs = XA + 2048;
        const uint32_t* WKs = XA + 3072;
        const uint32_t* WVs = XA + 4096;

        uint4 a0 = *(const uint4*)&XA[(wp*2    )*128 + lane*4];
        uint4 a1 = *(const uint4*)&XA[(wp*2 + 1)*128 + lane*4];
        #pragma unroll
        for (int nt = 0; nt < 8; nt++) {
            uint4 bb = *(const uint4*)&WQs[nt*128 + lane*4];
            mma_f16(accq[nt], a0.x, a0.y, a0.z, a0.w, bb.x, bb.y);
            mma_f16(accq[nt], a1.x, a1.y, a1.z, a1.w, bb.z, bb.w);
        }
        #pragma unroll
        for (int nt = 0; nt < 8; nt++) {
            uint4 bb = *(const uint4*)&WKs[nt*128 + lane*4];
            mma_f16(acck[nt], a0.x, a0.y, a0.z, a0.w, bb.x, bb.y);
            mma_f16(acck[nt], a1.x, a1.y, a1.z, a1.w, bb.z, bb.w);
        }
        #pragma unroll
        for (int nt = 0; nt < 8; nt++) {
            uint4 bb = *(const uint4*)&WVs[nt*128 + lane*4];
            mma_f16(accv[nt], a0.x, a0.y, a0.z, a0.w, bb.x, bb.y);
            mma_f16(accv[nt], a1.x, a1.y, a1.z, a1.w, bb.z, bb.w);
        }
    }
    #undef QKV_LOAD

    // ---- epilogue: bias (+ scale*log2e on q), emit fp16 fragment images ----
    const float qs = rsqrtf((float)D_) * 1.4426950408889634f;
    #pragma unroll
    for (int nt = 0; nt < 8; nt++) {
        float2 b2q = *(const float2*)(bq + h*E_ + nt*8 + 2*tg);
        float2 b2k = *(const float2*)(bk + h*E_ + nt*8 + 2*tg);
        float2 b2v = *(const float2*)(bv + h*E_ + nt*8 + 2*tg);
        accq[nt][0] = (accq[nt][0]+b2q.x)*qs;
        accq[nt][1] = (accq[nt][1]+b2q.y)*qs;
        accq[nt][2] = (accq[nt][2]+b2q.x)*qs;
        accq[nt][3] = (accq[nt][3]+b2q.y)*qs;
        acck[nt][0] += b2k.x; acck[nt][1] += b2k.y;
        acck[nt][2] += b2k.x; acck[nt][3] += b2k.y;
        accv[nt][0] += b2v.x; accv[nt][1] += b2v.y;
        accv[nt][2] += b2v.x; accv[nt][3] += b2v.y;
    }

    // Q: C-layout pairs ARE m16n8k16 A-frag pairs — direct uint4 stores
    const size_t qrb = ((size_t)bh*128 + qb2*8 + wp)*4;
    #pragma unroll
    for (int kc = 0; kc < 4; kc++) {
        uint4 w;
        w.x = hpack(accq[2*kc][1],   accq[2*kc][0]);
        w.y = hpack(accq[2*kc][3],   accq[2*kc][2]);
        w.z = hpack(accq[2*kc+1][1], accq[2*kc+1][0]);
        w.w = hpack(accq[2*kc+1][3], accq[2*kc+1][2]);
        *(uint4*)&g_qb[(qrb + kc)*128 + lane*4] = w;
    }

    // K/V: scatter into per-64-key-tile fp16 B-frag layout (validated)
    const size_t ktb = ((size_t)bh*32 + qb2*2 + (wp>>2))*2048;
    #pragma unroll
    for (int hh = 0; hh < 2; hh++) {
        int tk = (wp&3)*16 + hh*8 + g;
        int ntk = tk>>3, nl = tk&7;
        int kp3 = (tk>>1)&3, bregv = (tk>>3)&1, ktv = tk>>4;
        #pragma unroll
        for (int nt = 0; nt < 8; nt++) {
            int kc = nt>>1;
            g_kb[ktb + (size_t)((kc>>1)*8 + ntk)*128 + (nl*4+tg)*4 + (kc&1)*2 + (nt&1)] =
                hpack(acck[nt][hh*2+1], acck[nt][hh*2+0]);
            #pragma unroll
            for (int c = 0; c < 2; c++) {
                float mine = accv[nt][hh*2+c];
                float part = __shfl_xor_sync(0xffffffffu, mine, 4);
                if (!(g & 1)) {
                    int e = nt*8 + 2*tg + c;
                    g_vb[ktb + (size_t)((ktv>>1)*8 + (e>>3))*128
                             + ((e&7)*4 + kp3)*4 + (ktv&1)*2 + bregv] =
                        hpack(part, mine);
                }
            }
        }
    }
}

// ---------------- kernel 2: fp16 flash attention (4-stage + l-tree) --------
#define ATT_SMEM 65536

__global__ __launch_bounds__(256, 2) void attn_kernel()
{
    extern __shared__ uint32_t smu[];   // 4 stages x (2048 K + 2048 V) words
    const int qb = (S_/128 - 1) - blockIdx.x;
    const int h = blockIdx.y, b = blockIdx.z;
    const int bh = b*H_ + h;
    const int tid = threadIdx.x;
    const int wp = tid >> 5, lane = tid & 31;
    const int g = lane >> 2, tg = lane & 3;
    const int qrow0 = qb*128 + wp*16 + g;
    const uint32_t smem_base = s2u(smu);
    const uint32_t NEG  = 0xFBFFu;       // fp16 -65504 (ex2 -> 0)

    uint4 aq[4];
    const size_t qrb = ((size_t)bh*128 + qb*8 + wp)*4;
    #pragma unroll
    for (int kc = 0; kc < 4; kc++)
        aq[kc] = *(const uint4*)&g_qb[(qrb + kc)*128 + lane*4];

    float o[8][4];
    #pragma unroll
    for (int nt = 0; nt < 8; nt++) { o[nt][0]=o[nt][1]=o[nt][2]=o[nt][3]=0.f; }
    float l0 = 0.f, l1 = 0.f;

    const int nk = 2*qb + 2;

    #define KV_LOAD(stg, t) do {                                              \
        uint32_t dst = smem_base + (stg)*16384;                               \
        const uint4* ksrc = (const uint4*)(g_kb + ((size_t)bh*32 + (t))*2048);\
        const uint4* vsrc = (const uint4*)(g_vb + ((size_t)bh*32 + (t))*2048);\
        _Pragma("unroll")                                                     \
        for (int j = 0; j < 2; j++) {                                         \
            int i = tid + j*256;                                              \
            cp16(dst + i*16,        ksrc + i);                                \
            cp16(dst + 8192 + i*16, vsrc + i);                                \
        }                                                                     \
        asm volatile("cp.async.commit_group;");                               \
    } while (0)

    KV_LOAD(0, 0);
    KV_LOAD(1, 1);                    // nk >= 2 always
    if (nk > 2) KV_LOAD(2, 2);

    for (int t = 0; t < nk; t++) {
        if (t + 2 < nk)      asm volatile("cp.async.wait_group 2;");
        else if (t + 1 < nk) asm volatile("cp.async.wait_group 1;");
        else                 asm volatile("cp.async.wait_group 0;");
        __syncthreads();
        if (t + 3 < nk) KV_LOAD((t+3) & 3, t+3);

        const uint32_t* Kf = smu + (t & 3)*4096;
        const uint32_t* Vf = Kf + 2048;

        // --- S = Q @ K^T  (fp16 accum; packed C = PV A-frags) ---
        uint32_t sc[8][2];
        #pragma unroll
        for (int nt = 0; nt < 8; nt++) { sc[nt][0] = 0u; sc[nt][1] = 0u; }
        #pragma unroll
        for (int kc2 = 0; kc2 < 2; kc2++) {
            #pragma unroll
            for (int nt = 0; nt < 8; nt++) {
                uint4 bb = *(const uint4*)&Kf[(kc2*8 + nt)*128 + lane*4];
                mma_f16h(sc[nt], aq[2*kc2].x,   aq[2*kc2].y,
                                 aq[2*kc2].z,   aq[2*kc2].w,   bb.x, bb.y);
                mma_f16h(sc[nt], aq[2*kc2+1].x, aq[2*kc2+1].y,
                                 aq[2*kc2+1].z, aq[2*kc2+1].w, bb.z, bb.w);
            }
        }

        // --- causal mask (diagonal tiles): add -65504 to masked halves ---
        if (t >= 2*qb) {
            #pragma unroll
            for (int nt = 0; nt < 8; nt++) {
                int c = t*64 + nt*8 + 2*tg;
                uint32_t m0 = 0, m1 = 0;
                if (c     > qrow0)     m0 |= NEG;
                if (c + 1 > qrow0)     m0 |= NEG << 16;
                if (c     > qrow0 + 8) m1 |= NEG;
                if (c + 1 > qrow0 + 8) m1 |= NEG << 16;
                sc[nt][0] = hadd2(sc[nt][0], m0);
                sc[nt][1] = hadd2(sc[nt][1], m1);
            }
        }

        // --- softmax: ex2 directly on packed C ---
        uint32_t ph[8], pl[8];
        #pragma unroll
        for (int nt = 0; nt < 8; nt++) {
            ph[nt] = hex2(sc[nt][0]);
            pl[nt] = hex2(sc[nt][1]);
        }

        // --- O += P @ V (f32 accum) ---
        #pragma unroll
        for (int kt2 = 0; kt2 < 2; kt2++) {
            #pragma unroll
            for (int nt = 0; nt < 8; nt++) {
                uint4 bb = *(const uint4*)&Vf[(kt2*8 + nt)*128 + lane*4];
                mma_f16(o[nt], ph[4*kt2],   pl[4*kt2],
                               ph[4*kt2+1], pl[4*kt2+1], bb.x, bb.y);
                mma_f16(o[nt], ph[4*kt2+2], pl[4*kt2+2],
                               ph[4*kt2+3], pl[4*kt2+3], bb.z, bb.w);
            }
        }

        // --- l row-sums: hadd2 tree (ALU pipe, off the tensor unit) ---
        {
            uint32_t a = hadd2(hadd2(ph[0], ph[1]), hadd2(ph[2], ph[3]));
            uint32_t c = hadd2(hadd2(ph[4], ph[5]), hadd2(ph[6], ph[7]));
            float2 f0 = h2f2(hadd2(a, c));
            l0 += f0.x + f0.y;
            uint32_t d = hadd2(hadd2(pl[0], pl[1]), hadd2(pl[2], pl[3]));
            uint32_t e = hadd2(hadd2(pl[4], pl[5]), hadd2(pl[6], pl[7]));
            float2 f1 = h2f2(hadd2(d, e));
            l1 += f1.x + f1.y;
        }
    }
    #undef KV_LOAD

    // --- final 4-lane row-sum reduction + normalize ---
    l0 += __shfl_xor_sync(0xffffffffu, l0, 1);
    l0 += __shfl_xor_sync(0xffffffffu, l0, 2);
    l1 += __shfl_xor_sync(0xffffffffu, l1, 1);
    l1 += __shfl_xor_sync(0xffffffffu, l1, 2);
    const float inv0 = 1.f / l0, inv1 = 1.f / l1;
    #pragma unroll
    for (int nt = 0; nt < 8; nt++) {
        o[nt][0] *= inv0; o[nt][1] *= inv0;
        o[nt][2] *= inv1; o[nt][3] *= inv1;
    }
    // O C-frag pairs ARE proj A-frag pairs — direct fp16 packs
    const size_t rbg = (size_t)b*(S_/16) + qb*8 + wp;
    #pragma unroll
    for (int kc = 0; kc < 4; kc++) {
        uint4 w;
        w.x = hpack(o[2*kc][1],   o[2*kc][0]);
        w.y = hpack(o[2*kc][3],   o[2*kc][2]);
        w.z = hpack(o[2*kc+1][1], o[2*kc+1][0]);
        w.w = hpack(o[2*kc+1][3], o[2*kc+1][2]);
        *(uint4*)&g_atth[((rbg*32) + h*4 + kc)*128 + lane*4] = w;
    }
}

// ---------------- kernel 3: output projection (R12 config: 128-row, 2-stage)
#define PROJ_STAGE_W 4096
#define PROJ_SMEM_B  (2*PROJ_STAGE_W*4)

__global__ __launch_bounds__(256, 2) void proj_kernel(
    const float* __restrict__ bo, float* __restrict__ out)
{
    extern __shared__ uint32_t smu[];
    const int cb = blockIdx.x, mb = blockIdx.y;
    const int tid = threadIdx.x;
    const int wp = tid >> 5, lane = tid & 31;
    const int g = lane >> 2, tg = lane & 3;
    const uint32_t smem_base = s2u(smu);
    float acc[16][4] = {};

    #define PROJ_LOAD(st, kc) do {                                            \
        uint32_t dst = smem_base + (st)*(PROJ_STAGE_W*4);                     \
        _Pragma("unroll")                                                     \
        for (int j = 0; j < 2; j++) {                                         \
            int i = tid + j*256;                                              \
            int rb_l = i >> 6, ks = (i >> 5) & 1, off = i & 31;               \
            cp16(dst + i*16,                                                  \
                 g_atth + ((size_t)(mb*8 + rb_l)*32 + (kc)*2 + ks)*128 + off*4); \
            int nt_l = i >> 5, off2 = i & 31;                                 \
            cp16(dst + 8192 + i*16,                                           \
                 g_woh + ((size_t)(cb*16 + nt_l)*16 + (kc))*128 + off2*4);    \
        }                                                                     \
        asm volatile("cp.async.commit_group;");                               \
    } while (0)

    PROJ_LOAD(0, 0);
    for (int kc = 0; kc < 16; kc++) {
        const int st = kc & 1;
        if (kc + 1 < 16) { PROJ_LOAD(st^1, kc+1); asm volatile("cp.async.wait_group 1;"); }
        else             { asm volatile("cp.async.wait_group 0;"); }
        __syncthreads();
        const uint32_t* As = smu + st*PROJ_STAGE_W;
        const uint32_t* Bs = As + 2048;

        uint4 a0 = *(const uint4*)&As[(wp*2    )*128 + lane*4];
        uint4 a1 = *(const uint4*)&As[(wp*2 + 1)*128 + lane*4];
        #pragma unroll
        for (int nt = 0; nt < 16; nt++) {
            uint4 bb = *(const uint4*)&Bs[nt*128 + lane*4];
            mma_f16(acc[nt], a0.x, a0.y, a0.z, a0.w, bb.x, bb.y);
            mma_f16(acc[nt], a1.x, a1.y, a1.z, a1.w, bb.z, bb.w);
        }
        __syncthreads();
    }
    #undef PROJ_LOAD

    const int row0 = mb*128 + wp*16 + g;
    #pragma unroll
    for (int nt = 0; nt < 16; nt++) {
        int col = cb*128 + nt*8 + 2*tg;
        float2 b2 = *(const float2*)(bo + col);
        *(float2*)&out[(size_t)row0*D_ + col] =
            make_float2(acc[nt][0] + b2.x, acc[nt][1] + b2.y);
        *(float2*)&out[(size_t)(row0+8)*D_ + col] =
            make_float2(acc[nt][2] + b2.x, acc[nt][3] + b2.y);
    }
}

// ---------------------------------------------------------------------------
extern "C" void kernel_launch(void* const* d_in, const int* in_sizes, int n_in,
                              void* d_out, int out_size)
{
    const float* x  = (const float*)d_in[0];
    const float* Wq = (const float*)d_in[1];
    const float* bq = (const float*)d_in[2];
    const float* Wk = (const float*)d_in[3];
    const float* bk = (const float*)d_in[4];
    const float* Wv = (const float*)d_in[5];
    const float* bv = (const float*)d_in[6];
    const float* Wo = (const float*)d_in[7];
    const float* bo = (const float*)d_in[8];
    float* out = (float*)d_out;
    (void)in_sizes; (void)n_in; (void)out_size;

    cudaFuncSetAttribute(qkv_kernel,  cudaFuncAttributeMaxDynamicSharedMemorySize, QKV_SMEM_B);
    cudaFuncSetAttribute(attn_kernel, cudaFuncAttributeMaxDynamicSharedMemorySize, ATT_SMEM);
    cudaFuncSetAttribute(proj_kernel, cudaFuncAttributeMaxDynamicSharedMemorySize, PROJ_SMEM_B);

    prep_kernel<<<2560, 256>>>(x, Wq, Wk, Wv, Wo);

    dim3 g1(S_/128, H_, B_);
    qkv_kernel<<<g1, 256, QKV_SMEM_B>>>(bq, bk, bv);

    dim3 g2(S_/128, H_, B_);
    attn_kernel<<<g2, 256, ATT_SMEM>>>();

    dim3 g3(D_/128, (B_*S_)/128);
    proj_kernel<<<g3, 256, PROJ_SMEM_B>>>(bo, out);
}

// round 16
// speedup vs baseline: 1.0248x; 1.0248x over previous
#include <cuda_runtime.h>
#include <cuda_fp16.h>
#include <math.h>
#include <stdint.h>

#define B_ 4
#define S_ 2048
#define D_ 512
#define H_ 8
#define E_ 64

// ---------------- scratch (static, allocation-free) ----------------
__device__ __align__(16) uint32_t g_xh[B_*S_*D_/2];    // X, fp16 A-frag (k16)
__device__ __align__(16) uint32_t g_atth[B_*S_*D_/2];  // attn out, fp16 A-frag
__device__ __align__(16) uint32_t g_wqh[H_*D_*E_/2];   // weights, fp16 B-frag
__device__ __align__(16) uint32_t g_wkh[H_*D_*E_/2];
__device__ __align__(16) uint32_t g_wvh[H_*D_*E_/2];
__device__ __align__(16) uint32_t g_woh[D_*D_/2];
// fp16x2 fragment images for the attention kernel
__device__ __align__(16) uint32_t g_qb[B_*H_*S_*E_/2]; // Q A-frag, scaled
__device__ __align__(16) uint32_t g_kb[B_*H_*S_*E_/2]; // K B-frag per 64-key tile
__device__ __align__(16) uint32_t g_vb[B_*H_*S_*E_/2]; // V B-frag per 64-key tile

// ---------------- helpers ----------------
__device__ __forceinline__ uint32_t hpack(float hi, float lo) {
    uint32_t u;
    asm("cvt.rn.f16x2.f32 %0, %1, %2;" : "=r"(u) : "f"(hi), "f"(lo));
    return u;
}
__device__ __forceinline__ uint32_t hex2(uint32_t x) {   // 2^x on fp16x2 pair
    uint32_t y; asm("ex2.approx.f16x2 %0, %1;" : "=r"(y) : "r"(x)); return y;
}
__device__ __forceinline__ uint32_t hadd2(uint32_t a, uint32_t b) {
    uint32_t y; asm("add.rn.f16x2 %0, %1, %2;" : "=r"(y) : "r"(a), "r"(b)); return y;
}
__device__ __forceinline__ float2 h2f2(uint32_t u) {
    __half2 h = *(__half2*)&u;
    return __half22float2(h);
}
__device__ __forceinline__ void mma_f16(float c[4], uint32_t a0, uint32_t a1,
                                        uint32_t a2, uint32_t a3,
                                        uint32_t b0, uint32_t b1) {
    asm volatile(
        "mma.sync.aligned.m16n8k16.row.col.f32.f16.f16.f32 "
        "{%0,%1,%2,%3}, {%4,%5,%6,%7}, {%8,%9}, {%0,%1,%2,%3};"
        : "+f"(c[0]), "+f"(c[1]), "+f"(c[2]), "+f"(c[3])
        : "r"(a0), "r"(a1), "r"(a2), "r"(a3), "r"(b0), "r"(b1));
}
// fp16-accumulate variant: C/D are two packed f16x2 regs (rows g / g+8)
__device__ __forceinline__ void mma_f16h(uint32_t c[2], uint32_t a0, uint32_t a1,
                                         uint32_t a2, uint32_t a3,
                                         uint32_t b0, uint32_t b1) {
    asm volatile(
        "mma.sync.aligned.m16n8k16.row.col.f16.f16.f16.f16 "
        "{%0,%1}, {%2,%3,%4,%5}, {%6,%7}, {%0,%1};"
        : "+r"(c[0]), "+r"(c[1])
        : "r"(a0), "r"(a1), "r"(a2), "r"(a3), "r"(b0), "r"(b1));
}
__device__ __forceinline__ void cp16(uint32_t dst, const void* src) {
    asm volatile("cp.async.cg.shared.global [%0], [%1], 16;\n" :: "r"(dst), "l"(src));
}
__device__ __forceinline__ uint32_t s2u(const void* p) {
    uint32_t a;
    asm("{ .reg .u64 t; cvta.to.shared.u64 t, %1; cvt.u32.u64 %0, t; }" : "=r"(a) : "l"(p));
    return a;
}

// ---------------- kernel 0: fused prep (weights + X) -----------------------
__global__ __launch_bounds__(256) void prep_kernel(
    const float* __restrict__ x,
    const float* __restrict__ Wq, const float* __restrict__ Wk,
    const float* __restrict__ Wv, const float* __restrict__ Wo)
{
    int blk = blockIdx.x;
    if (blk < 512) {
        int i = blk*256 + threadIdx.x;       // 0..131071 (pairs along k)
        {   // Wq/Wk/Wv: [h][d][e], k=d(512), n=e(64)
            int h = i >> 14, p = i & 16383;
            int e = p & 63, d = (p >> 6) * 2;
            int kc = d >> 5, ks16 = (d >> 4) & 1, kk = d & 15;
            int half = kk >> 3, tg = (kk >> 1) & 3;
            int lane = (e & 7)*4 + tg, nt = e >> 3;
            int idx = h*16384 + kc*1024 + nt*128 + lane*4 + ks16*2 + half;
            size_t s0 = (size_t)h*32768 + (size_t)d*64 + e;
            g_wqh[idx] = hpack(Wq[s0 + 64], Wq[s0]);
            g_wkh[idx] = hpack(Wk[s0 + 64], Wk[s0]);
            g_wvh[idx] = hpack(Wv[s0 + 64], Wv[s0]);
        }
        {   // Wo: [d][n], k=d(512), n(512)
            int n = i & 511, d = (i >> 9) * 2;
            int kc = d >> 5, ks16 = (d >> 4) & 1, kk = d & 15;
            int half = kk >> 3, tg = (kk >> 1) & 3;
            int lane = (n & 7)*4 + tg, ntg = n >> 3;
            int idx = (ntg*16 + kc)*128 + lane*4 + ks16*2 + half;
            size_t s0 = (size_t)d*512 + n;
            g_woh[idx] = hpack(Wo[s0 + 512], Wo[s0]);
        }
    } else {
        int i = (blk - 512)*256 + threadIdx.x;   // uint4 index, 512K total
        int lane = i & 31, ksg = (i >> 5) & 31, rbg = i >> 10;
        int g = lane >> 2, tg = lane & 3;
        const float* src = x + ((size_t)rbg*16 + g)*D_ + ksg*16 + 2*tg;
        uint4 o;
        o.x = hpack(src[1],          src[0]);
        o.y = hpack(src[8*D_ + 1],   src[8*D_]);
        o.z = hpack(src[9],          src[8]);
        o.w = hpack(src[8*D_ + 9],   src[8*D_ + 8]);
        *(uint4*)&g_xh[(size_t)i*4] = o;
    }
}

// ---------------- kernel 1: QKV, fp16 m16n8k16, 3-stage cp.async -----------
// Epilogue: K/V fragment words scattered into SMEM, then coalesced uint4 STG.
#define QKV_STAGE_W 5120
#define QKV_SMEM_B  (3*QKV_STAGE_W*4)

__global__ __launch_bounds__(256, 2) void qkv_kernel(
    const float* __restrict__ bq, const float* __restrict__ bk,
    const float* __restrict__ bv)
{
    extern __shared__ uint32_t smu[];
    const int qb2 = blockIdx.x, h = blockIdx.y, b = blockIdx.z;
    const int bh = b*H_ + h;
    const int tid = threadIdx.x;
    const int wp = tid >> 5, lane = tid & 31;
    const int g = lane >> 2, tg = lane & 3;
    const uint32_t smem_base = s2u(smu);
    const size_t rbg0 = (size_t)b*(S_/16) + qb2*8;
    const size_t wbase = (size_t)h * 16384;

    float accq[8][4] = {}, acck[8][4] = {}, accv[8][4] = {};

    #define QKV_LOAD(stg, kc) do {                                            \
        uint32_t dst = smem_base + (stg)*(QKV_STAGE_W*4);                     \
        _Pragma("unroll")                                                     \
        for (int j = 0; j < 2; j++) {                                         \
            int i = tid + j*256;                                              \
            int rb = i >> 6, ks = (i >> 5) & 1, off = i & 31;                 \
            cp16(dst + i*16,                                                  \
                 g_xh + ((rbg0 + rb)*32 + (kc)*2 + ks)*128 + off*4);          \
        }                                                                     \
        cp16(dst + 8192  + tid*16, g_wqh + wbase + (kc)*1024 + tid*4);        \
        cp16(dst + 12288 + tid*16, g_wkh + wbase + (kc)*1024 + tid*4);        \
        cp16(dst + 16384 + tid*16, g_wvh + wbase + (kc)*1024 + tid*4);        \
        asm volatile("cp.async.commit_group;");                               \
    } while (0)

    QKV_LOAD(0, 0);
    QKV_LOAD(1, 1);
    for (int kc = 0; kc < 16; kc++) {
        if (kc + 1 < 16) asm volatile("cp.async.wait_group 1;");
        else             asm volatile("cp.async.wait_group 0;");
        __syncthreads();
        if (kc + 2 < 16) QKV_LOAD((kc + 2) % 3, kc + 2);

        const uint32_t* XA  = smu + (kc % 3)*QKV_STAGE_W;
        const uint32_t* WQs = XA + 2048;
        const uint32_t* WKs = XA + 3072;
        const uint32_t* WVs = XA + 4096;

        uint4 a0 = *(const uint4*)&XA[(wp*2    )*128 + lane*4];
        uint4 a1 = *(const uint4*)&XA[(wp*2 + 1)*128 + lane*4];
        #pragma unroll
        for (int nt = 0; nt < 8; nt++) {
            uint4 bb = *(const uint4*)&WQs[nt*128 + lane*4];
            mma_f16(accq[nt], a0.x, a0.y, a0.z, a0.w, bb.x, bb.y);
            mma_f16(accq[nt], a1.x, a1.y, a1.z, a1.w, bb.z, bb.w);
        }
        #pragma unroll
        for (int nt = 0; nt < 8; nt++) {
            uint4 bb = *(const uint4*)&WKs[nt*128 + lane*4];
            mma_f16(acck[nt], a0.x, a0.y, a0.z, a0.w, bb.x, bb.y);
            mma_f16(acck[nt], a1.x, a1.y, a1.z, a1.w, bb.z, bb.w);
        }
        #pragma unroll
        for (int nt = 0; nt < 8; nt++) {
            uint4 bb = *(const uint4*)&WVs[nt*128 + lane*4];
            mma_f16(accv[nt], a0.x, a0.y, a0.z, a0.w, bb.x, bb.y);
            mma_f16(accv[nt], a1.x, a1.y, a1.z, a1.w, bb.z, bb.w);
        }
    }
    #undef QKV_LOAD

    // ---- epilogue: bias (+ scale*log2e on q), emit fp16 fragment images ----
    const float qs = rsqrtf((float)D_) * 1.4426950408889634f;
    #pragma unroll
    for (int nt = 0; nt < 8; nt++) {
        float2 b2q = *(const float2*)(bq + h*E_ + nt*8 + 2*tg);
        float2 b2k = *(const float2*)(bk + h*E_ + nt*8 + 2*tg);
        float2 b2v = *(const float2*)(bv + h*E_ + nt*8 + 2*tg);
        accq[nt][0] = (accq[nt][0]+b2q.x)*qs;
        accq[nt][1] = (accq[nt][1]+b2q.y)*qs;
        accq[nt][2] = (accq[nt][2]+b2q.x)*qs;
        accq[nt][3] = (accq[nt][3]+b2q.y)*qs;
        acck[nt][0] += b2k.x; acck[nt][1] += b2k.y;
        acck[nt][2] += b2k.x; acck[nt][3] += b2k.y;
        accv[nt][0] += b2v.x; accv[nt][1] += b2v.y;
        accv[nt][2] += b2v.x; accv[nt][3] += b2v.y;
    }

    // Q: C-layout pairs ARE m16n8k16 A-frag pairs — direct uint4 stores
    const size_t qrb = ((size_t)bh*128 + qb2*8 + wp)*4;
    #pragma unroll
    for (int kc = 0; kc < 4; kc++) {
        uint4 w;
        w.x = hpack(accq[2*kc][1],   accq[2*kc][0]);
        w.y = hpack(accq[2*kc][3],   accq[2*kc][2]);
        w.z = hpack(accq[2*kc+1][1], accq[2*kc+1][0]);
        w.w = hpack(accq[2*kc+1][3], accq[2*kc+1][2]);
        *(uint4*)&g_qb[(qrb + kc)*128 + lane*4] = w;
    }

    // K/V: scatter fragment words into SMEM images (Ksm[4096] Vsm[4096]),
    // then coalesced uint4 stores to global. Pipeline smem is dead here.
    __syncthreads();
    uint32_t* Ksm = smu;
    uint32_t* Vsm = smu + 4096;
    const int wt = (wp >> 2) * 2048;   // which 64-key tile image
    #pragma unroll
    for (int hh = 0; hh < 2; hh++) {
        int tk = (wp&3)*16 + hh*8 + g;
        int ntk = tk>>3, nl = tk&7;
        int kp3 = (tk>>1)&3, bregv = (tk>>3)&1, ktv = tk>>4;
        #pragma unroll
        for (int nt = 0; nt < 8; nt++) {
            int kc = nt>>1;
            Ksm[wt + ((kc>>1)*8 + ntk)*128 + (nl*4+tg)*4 + (kc&1)*2 + (nt&1)] =
                hpack(acck[nt][hh*2+1], acck[nt][hh*2+0]);
            #pragma unroll
            for (int c = 0; c < 2; c++) {
                float mine = accv[nt][hh*2+c];
                float part = __shfl_xor_sync(0xffffffffu, mine, 4);
                if (!(g & 1)) {
                    int e = nt*8 + 2*tg + c;
                    Vsm[wt + ((ktv>>1)*8 + (e>>3))*128
                           + ((e&7)*4 + kp3)*4 + (ktv&1)*2 + bregv] =
                        hpack(part, mine);
                }
            }
        }
    }
    __syncthreads();
    const size_t ktb0 = ((size_t)bh*32 + qb2*2)*2048;
    #pragma unroll
    for (int j = 0; j < 4; j++) {
        int i = tid + j*256;             // uint4 index, 1024 total
        *(uint4*)&g_kb[ktb0 + i*4] = ((const uint4*)Ksm)[i];
        *(uint4*)&g_vb[ktb0 + i*4] = ((const uint4*)Vsm)[i];
    }
}

// ---------------- kernel 2: fp16 flash attention (4-stage + l-tree) --------
#define ATT_SMEM 65536

__global__ __launch_bounds__(256, 2) void attn_kernel()
{
    extern __shared__ uint32_t smu[];   // 4 stages x (2048 K + 2048 V) words
    const int qb = (S_/128 - 1) - blockIdx.x;
    const int h = blockIdx.y, b = blockIdx.z;
    const int bh = b*H_ + h;
    const int tid = threadIdx.x;
    const int wp = tid >> 5, lane = tid & 31;
    const int g = lane >> 2, tg = lane & 3;
    const int qrow0 = qb*128 + wp*16 + g;
    const uint32_t smem_base = s2u(smu);
    const uint32_t NEG  = 0xFBFFu;       // fp16 -65504 (ex2 -> 0)

    uint4 aq[4];
    const size_t qrb = ((size_t)bh*128 + qb*8 + wp)*4;
    #pragma unroll
    for (int kc = 0; kc < 4; kc++)
        aq[kc] = *(const uint4*)&g_qb[(qrb + kc)*128 + lane*4];

    float o[8][4];
    #pragma unroll
    for (int nt = 0; nt < 8; nt++) { o[nt][0]=o[nt][1]=o[nt][2]=o[nt][3]=0.f; }
    float l0 = 0.f, l1 = 0.f;

    const int nk = 2*qb + 2;

    #define KV_LOAD(stg, t) do {                                              \
        uint32_t dst = smem_base + (stg)*16384;                               \
        const uint4* ksrc = (const uint4*)(g_kb + ((size_t)bh*32 + (t))*2048);\
        const uint4* vsrc = (const uint4*)(g_vb + ((size_t)bh*32 + (t))*2048);\
        _Pragma("unroll")                                                     \
        for (int j = 0; j < 2; j++) {                                         \
            int i = tid + j*256;                                              \
            cp16(dst + i*16,        ksrc + i);                                \
            cp16(dst + 8192 + i*16, vsrc + i);                                \
        }                                                                     \
        asm volatile("cp.async.commit_group;");                               \
    } while (0)

    KV_LOAD(0, 0);
    KV_LOAD(1, 1);                    // nk >= 2 always
    if (nk > 2) KV_LOAD(2, 2);

    for (int t = 0; t < nk; t++) {
        if (t + 2 < nk)      asm volatile("cp.async.wait_group 2;");
        else if (t + 1 < nk) asm volatile("cp.async.wait_group 1;");
        else                 asm volatile("cp.async.wait_group 0;");
        __syncthreads();
        if (t + 3 < nk) KV_LOAD((t+3) & 3, t+3);

        const uint32_t* Kf = smu + (t & 3)*4096;
        const uint32_t* Vf = Kf + 2048;

        // --- S = Q @ K^T  (fp16 accum; packed C = PV A-frags) ---
        uint32_t sc[8][2];
        #pragma unroll
        for (int nt = 0; nt < 8; nt++) { sc[nt][0] = 0u; sc[nt][1] = 0u; }
        #pragma unroll
        for (int kc2 = 0; kc2 < 2; kc2++) {
            #pragma unroll
            for (int nt = 0; nt < 8; nt++) {
                uint4 bb = *(const uint4*)&Kf[(kc2*8 + nt)*128 + lane*4];
                mma_f16h(sc[nt], aq[2*kc2].x,   aq[2*kc2].y,
                                 aq[2*kc2].z,   aq[2*kc2].w,   bb.x, bb.y);
                mma_f16h(sc[nt], aq[2*kc2+1].x, aq[2*kc2+1].y,
                                 aq[2*kc2+1].z, aq[2*kc2+1].w, bb.z, bb.w);
            }
        }

        // --- causal mask (diagonal tiles): add -65504 to masked halves ---
        if (t >= 2*qb) {
            #pragma unroll
            for (int nt = 0; nt < 8; nt++) {
                int c = t*64 + nt*8 + 2*tg;
                uint32_t m0 = 0, m1 = 0;
                if (c     > qrow0)     m0 |= NEG;
                if (c + 1 > qrow0)     m0 |= NEG << 16;
                if (c     > qrow0 + 8) m1 |= NEG;
                if (c + 1 > qrow0 + 8) m1 |= NEG << 16;
                sc[nt][0] = hadd2(sc[nt][0], m0);
                sc[nt][1] = hadd2(sc[nt][1], m1);
            }
        }

        // --- softmax: ex2 directly on packed C ---
        uint32_t ph[8], pl[8];
        #pragma unroll
        for (int nt = 0; nt < 8; nt++) {
            ph[nt] = hex2(sc[nt][0]);
            pl[nt] = hex2(sc[nt][1]);
        }

        // --- O += P @ V (f32 accum) ---
        #pragma unroll
        for (int kt2 = 0; kt2 < 2; kt2++) {
            #pragma unroll
            for (int nt = 0; nt < 8; nt++) {
                uint4 bb = *(const uint4*)&Vf[(kt2*8 + nt)*128 + lane*4];
                mma_f16(o[nt], ph[4*kt2],   pl[4*kt2],
                               ph[4*kt2+1], pl[4*kt2+1], bb.x, bb.y);
                mma_f16(o[nt], ph[4*kt2+2], pl[4*kt2+2],
                               ph[4*kt2+3], pl[4*kt2+3], bb.z, bb.w);
            }
        }

        // --- l row-sums: hadd2 tree (ALU pipe, off the tensor unit) ---
        {
            uint32_t a = hadd2(hadd2(ph[0], ph[1]), hadd2(ph[2], ph[3]));
            uint32_t c = hadd2(hadd2(ph[4], ph[5]), hadd2(ph[6], ph[7]));
            float2 f0 = h2f2(hadd2(a, c));
            l0 += f0.x + f0.y;
            uint32_t d = hadd2(hadd2(pl[0], pl[1]), hadd2(pl[2], pl[3]));
            uint32_t e = hadd2(hadd2(pl[4], pl[5]), hadd2(pl[6], pl[7]));
            float2 f1 = h2f2(hadd2(d, e));
            l1 += f1.x + f1.y;
        }
    }
    #undef KV_LOAD

    // --- final 4-lane row-sum reduction + normalize ---
    l0 += __shfl_xor_sync(0xffffffffu, l0, 1);
    l0 += __shfl_xor_sync(0xffffffffu, l0, 2);
    l1 += __shfl_xor_sync(0xffffffffu, l1, 1);
    l1 += __shfl_xor_sync(0xffffffffu, l1, 2);
    const float inv0 = 1.f / l0, inv1 = 1.f / l1;
    #pragma unroll
    for (int nt = 0; nt < 8; nt++) {
        o[nt][0] *= inv0; o[nt][1] *= inv0;
        o[nt][2] *= inv1; o[nt][3] *= inv1;
    }
    // O C-frag pairs ARE proj A-frag pairs — direct fp16 packs
    const size_t rbg = (size_t)b*(S_/16) + qb*8 + wp;
    #pragma unroll
    for (int kc = 0; kc < 4; kc++) {
        uint4 w;
        w.x = hpack(o[2*kc][1],   o[2*kc][0]);
        w.y = hpack(o[2*kc][3],   o[2*kc][2]);
        w.z = hpack(o[2*kc+1][1], o[2*kc+1][0]);
        w.w = hpack(o[2*kc+1][3], o[2*kc+1][2]);
        *(uint4*)&g_atth[((rbg*32) + h*4 + kc)*128 + lane*4] = w;
    }
}

// ---------------- kernel 3: output projection (128-row, 2-stage) -----------
#define PROJ_STAGE_W 4096
#define PROJ_SMEM_B  (2*PROJ_STAGE_W*4)

__global__ __launch_bounds__(256, 2) void proj_kernel(
    const float* __restrict__ bo, float* __restrict__ out)
{
    extern __shared__ uint32_t smu[];
    const int cb = blockIdx.x, mb = blockIdx.y;
    const int tid = threadIdx.x;
    const int wp = tid >> 5, lane = tid & 31;
    const int g = lane >> 2, tg = lane & 3;
    const uint32_t smem_base = s2u(smu);
    float acc[16][4] = {};

    #define PROJ_LOAD(st, kc) do {                                            \
        uint32_t dst = smem_base + (st)*(PROJ_STAGE_W*4);                     \
        _Pragma("unroll")                                                     \
        for (int j = 0; j < 2; j++) {                                         \
            int i = tid + j*256;                                              \
            int rb_l = i >> 6, ks = (i >> 5) & 1, off = i & 31;               \
            cp16(dst + i*16,                                                  \
                 g_atth + ((size_t)(mb*8 + rb_l)*32 + (kc)*2 + ks)*128 + off*4); \
            int nt_l = i >> 5, off2 = i & 31;                                 \
            cp16(dst + 8192 + i*16,                                           \
                 g_woh + ((size_t)(cb*16 + nt_l)*16 + (kc))*128 + off2*4);    \
        }                                                                     \
        asm volatile("cp.async.commit_group;");                               \
    } while (0)

    PROJ_LOAD(0, 0);
    for (int kc = 0; kc < 16; kc++) {
        const int st = kc & 1;
        if (kc + 1 < 16) { PROJ_LOAD(st^1, kc+1); asm volatile("cp.async.wait_group 1;"); }
        else             { asm volatile("cp.async.wait_group 0;"); }
        __syncthreads();
        const uint32_t* As = smu + st*PROJ_STAGE_W;
        const uint32_t* Bs = As + 2048;

        uint4 a0 = *(const uint4*)&As[(wp*2    )*128 + lane*4];
        uint4 a1 = *(const uint4*)&As[(wp*2 + 1)*128 + lane*4];
        #pragma unroll
        for (int nt = 0; nt < 16; nt++) {
            uint4 bb = *(const uint4*)&Bs[nt*128 + lane*4];
            mma_f16(acc[nt], a0.x, a0.y, a0.z, a0.w, bb.x, bb.y);
            mma_f16(acc[nt], a1.x, a1.y, a1.z, a1.w, bb.z, bb.w);
        }
        __syncthreads();
    }
    #undef PROJ_LOAD

    const int row0 = mb*128 + wp*16 + g;
    #pragma unroll
    for (int nt = 0; nt < 16; nt++) {
        int col = cb*128 + nt*8 + 2*tg;
        float2 b2 = *(const float2*)(bo + col);
        *(float2*)&out[(size_t)row0*D_ + col] =
            make_float2(acc[nt][0] + b2.x, acc[nt][1] + b2.y);
        *(float2*)&out[(size_t)(row0+8)*D_ + col] =
            make_float2(acc[nt][2] + b2.x, acc[nt][3] + b2.y);
    }
}

// ---------------------------------------------------------------------------
extern "C" void kernel_launch(void* const* d_in, const int* in_sizes, int n_in,
                              void* d_out, int out_size)
{
    const float* x  = (const float*)d_in[0];
    const float* Wq = (const float*)d_in[1];
    const float* bq = (const float*)d_in[2];
    const float* Wk = (const float*)d_in[3];
    const float* bk = (const float*)d_in[4];
    const float* Wv = (const float*)d_in[5];
    const float* bv = (const float*)d_in[6];
    const float* Wo = (const float*)d_in[7];
    const float* bo = (const float*)d_in[8];
    float* out = (float*)d_out;
    (void)in_sizes; (void)n_in; (void)out_size;

    cudaFuncSetAttribute(qkv_kernel,  cudaFuncAttributeMaxDynamicSharedMemorySize, QKV_SMEM_B);
    cudaFuncSetAttribute(attn_kernel, cudaFuncAttributeMaxDynamicSharedMemorySize, ATT_SMEM);
    cudaFuncSetAttribute(proj_kernel, cudaFuncAttributeMaxDynamicSharedMemorySize, PROJ_SMEM_B);

    prep_kernel<<<2560, 256>>>(x, Wq, Wk, Wv, Wo);

    dim3 g1(S_/128, H_, B_);
    qkv_kernel<<<g1, 256, QKV_SMEM_B>>>(bq, bk, bv);

    dim3 g2(S_/128, H_, B_);
    attn_kernel<<<g2, 256, ATT_SMEM>>>();

    dim3 g3(D_/128, (B_*S_)/128);
    proj_kernel<<<g3, 256, PROJ_SMEM_B>>>(bo, out);
}